// round 2
// baseline (speedup 1.0000x reference)
#include <cuda_runtime.h>
#include <math.h>

#define NTOK 2048
#define DMODEL 2048
#define NH 32
#define NKV 8
#define HDIM 64
#define QD 2048   // NH*HDIM
#define KD 512    // NKV*HDIM
#define NE 8
#define FF 7168
#define RMS_EPS 1e-5f

// ---------------- scratch (device globals: no allocations allowed) ----------------
__device__ float g_hn  [NTOK * DMODEL];   // rmsnorm1 out
__device__ float g_q   [NTOK * QD];
__device__ float g_k   [NTOK * KD];
__device__ float g_v   [NTOK * KD];
__device__ float g_attn[NTOK * QD];       // attention out (pre-Wo)
__device__ float g_h1  [NTOK * DMODEL];   // residual after attention
__device__ float g_hn2 [NTOK * DMODEL];   // rmsnorm2 out
__device__ float g_comb[NTOK * NE];       // combine weights
__device__ int   g_cnt [NE];
__device__ int   g_idx [NE * NTOK];
__device__ float g_act [NTOK * FF];       // gate -> silu(gate)*up
__device__ float g_act2[NTOK * FF];       // up

// ---------------- rmsnorm ----------------
__global__ void rmsnorm_kernel(const float* __restrict__ x, const float* __restrict__ w,
                               float* __restrict__ y) {
    int row = blockIdx.x;
    int tid = threadIdx.x;
    const float* xr = x + (size_t)row * DMODEL;
    float s = 0.f;
    for (int i = tid; i < DMODEL; i += 256) { float v = xr[i]; s += v * v; }
    // warp reduce
    for (int off = 16; off > 0; off >>= 1) s += __shfl_xor_sync(0xffffffffu, s, off);
    __shared__ float sh[8];
    if ((tid & 31) == 0) sh[tid >> 5] = s;
    __syncthreads();
    float tot = 0.f;
    for (int k = 0; k < 8; k++) tot += sh[k];
    float inv = rsqrtf(tot / (float)DMODEL + RMS_EPS);
    float* yr = y + (size_t)row * DMODEL;
    for (int i = tid; i < DMODEL; i += 256) yr[i] = xr[i] * inv * w[i];
}

// ---------------- generic 128x128x8 fp32 GEMM, C = A@B (+res) ----------------
template <bool ADD_RES>
__global__ void gemm128(const float* __restrict__ A, const float* __restrict__ B,
                        const float* __restrict__ R, float* __restrict__ C,
                        int M, int Nn, int K) {
    __shared__ float As[8][128];
    __shared__ float Bs[8][128];
    const int tid = threadIdx.x;
    const int tx = tid & 15, ty = tid >> 4;
    float acc[8][8];
#pragma unroll
    for (int i = 0; i < 8; i++)
#pragma unroll
        for (int j = 0; j < 8; j++) acc[i][j] = 0.f;

    const int arow = tid >> 1;
    const int acol = (tid & 1) << 2;
    const int brow = tid >> 5;
    const int bcol = (tid & 31) << 2;
    const float* Ap = A + (size_t)(blockIdx.y * 128 + arow) * K + acol;
    const float* Bp = B + (size_t)brow * Nn + blockIdx.x * 128 + bcol;

    for (int k0 = 0; k0 < K; k0 += 8) {
        float4 a4 = *(const float4*)(Ap + k0);
        float4 b4 = *(const float4*)(Bp + (size_t)k0 * Nn);
        As[acol + 0][arow] = a4.x;
        As[acol + 1][arow] = a4.y;
        As[acol + 2][arow] = a4.z;
        As[acol + 3][arow] = a4.w;
        *(float4*)&Bs[brow][bcol] = b4;
        __syncthreads();
#pragma unroll
        for (int kk = 0; kk < 8; kk++) {
            float ar[8], br[8];
#pragma unroll
            for (int i = 0; i < 8; i++) ar[i] = As[kk][ty * 8 + i];
#pragma unroll
            for (int j = 0; j < 8; j++) br[j] = Bs[kk][tx * 8 + j];
#pragma unroll
            for (int i = 0; i < 8; i++)
#pragma unroll
                for (int j = 0; j < 8; j++) acc[i][j] += ar[i] * br[j];
        }
        __syncthreads();
    }
#pragma unroll
    for (int i = 0; i < 8; i++) {
        int r = blockIdx.y * 128 + ty * 8 + i;
#pragma unroll
        for (int j = 0; j < 8; j++) {
            size_t off = (size_t)r * Nn + blockIdx.x * 128 + tx * 8 + j;
            C[off] = ADD_RES ? (acc[i][j] + R[off]) : acc[i][j];
        }
    }
}

// ---------------- MoE: gathered-row GEMM  C[r] = X[idx[r]] @ B ----------------
__global__ void gemm_gather(const float* __restrict__ X, const float* __restrict__ B,
                            float* __restrict__ C, const int* __restrict__ idx,
                            const int* __restrict__ cntp, int K, int Nn) {
    const int cnt = *cntp;
    if ((int)(blockIdx.y * 128) >= cnt) return;
    __shared__ float As[8][128];
    __shared__ float Bs[8][128];
    const int tid = threadIdx.x;
    const int tx = tid & 15, ty = tid >> 4;
    float acc[8][8];
#pragma unroll
    for (int i = 0; i < 8; i++)
#pragma unroll
        for (int j = 0; j < 8; j++) acc[i][j] = 0.f;

    const int arow = tid >> 1;
    const int acol = (tid & 1) << 2;
    const int brow = tid >> 5;
    const int bcol = (tid & 31) << 2;
    int r0 = blockIdx.y * 128 + arow;
    int token = idx[r0 < cnt ? r0 : 0];
    const float* Ap = X + (size_t)token * K + acol;
    const float* Bp = B + (size_t)brow * Nn + blockIdx.x * 128 + bcol;

    for (int k0 = 0; k0 < K; k0 += 8) {
        float4 a4 = *(const float4*)(Ap + k0);
        float4 b4 = *(const float4*)(Bp + (size_t)k0 * Nn);
        As[acol + 0][arow] = a4.x;
        As[acol + 1][arow] = a4.y;
        As[acol + 2][arow] = a4.z;
        As[acol + 3][arow] = a4.w;
        *(float4*)&Bs[brow][bcol] = b4;
        __syncthreads();
#pragma unroll
        for (int kk = 0; kk < 8; kk++) {
            float ar[8], br[8];
#pragma unroll
            for (int i = 0; i < 8; i++) ar[i] = As[kk][ty * 8 + i];
#pragma unroll
            for (int j = 0; j < 8; j++) br[j] = Bs[kk][tx * 8 + j];
#pragma unroll
            for (int i = 0; i < 8; i++)
#pragma unroll
                for (int j = 0; j < 8; j++) acc[i][j] += ar[i] * br[j];
        }
        __syncthreads();
    }
#pragma unroll
    for (int i = 0; i < 8; i++) {
        int r = blockIdx.y * 128 + ty * 8 + i;
        if (r < cnt) {
#pragma unroll
            for (int j = 0; j < 8; j++)
                C[(size_t)r * Nn + blockIdx.x * 128 + tx * 8 + j] = acc[i][j];
        }
    }
}

// ---------------- MoE: down-proj + weighted scatter-add into out ----------------
__global__ void gemm_down(const float* __restrict__ Act, const float* __restrict__ B,
                          float* __restrict__ Out, const int* __restrict__ idx,
                          const int* __restrict__ cntp, const float* __restrict__ comb,
                          int e) {
    const int cnt = *cntp;
    if ((int)(blockIdx.y * 128) >= cnt) return;
    __shared__ float As[8][128];
    __shared__ float Bs[8][128];
    const int tid = threadIdx.x;
    const int tx = tid & 15, ty = tid >> 4;
    float acc[8][8];
#pragma unroll
    for (int i = 0; i < 8; i++)
#pragma unroll
        for (int j = 0; j < 8; j++) acc[i][j] = 0.f;

    const int arow = tid >> 1;
    const int acol = (tid & 1) << 2;
    const int brow = tid >> 5;
    const int bcol = (tid & 31) << 2;
    int r0 = blockIdx.y * 128 + arow;
    int rr = r0 < cnt ? r0 : 0;
    const float* Ap = Act + (size_t)rr * FF + acol;
    const float* Bp = B + (size_t)brow * DMODEL + blockIdx.x * 128 + bcol;

    for (int k0 = 0; k0 < FF; k0 += 8) {
        float4 a4 = *(const float4*)(Ap + k0);
        float4 b4 = *(const float4*)(Bp + (size_t)k0 * DMODEL);
        As[acol + 0][arow] = a4.x;
        As[acol + 1][arow] = a4.y;
        As[acol + 2][arow] = a4.z;
        As[acol + 3][arow] = a4.w;
        *(float4*)&Bs[brow][bcol] = b4;
        __syncthreads();
#pragma unroll
        for (int kk = 0; kk < 8; kk++) {
            float ar[8], br[8];
#pragma unroll
            for (int i = 0; i < 8; i++) ar[i] = As[kk][ty * 8 + i];
#pragma unroll
            for (int j = 0; j < 8; j++) br[j] = Bs[kk][tx * 8 + j];
#pragma unroll
            for (int i = 0; i < 8; i++)
#pragma unroll
                for (int j = 0; j < 8; j++) acc[i][j] += ar[i] * br[j];
        }
        __syncthreads();
    }
#pragma unroll
    for (int i = 0; i < 8; i++) {
        int r = blockIdx.y * 128 + ty * 8 + i;
        if (r < cnt) {
            int t = idx[r];
            float w = comb[t * NE + e];
#pragma unroll
            for (int j = 0; j < 8; j++) {
                size_t off = (size_t)t * DMODEL + blockIdx.x * 128 + tx * 8 + j;
                Out[off] += w * acc[i][j];
            }
        }
    }
}

// ---------------- RoPE (in place) ----------------
__global__ void rope_kernel(float* x, const int* __restrict__ pos, int heads) {
    int s = blockIdx.x;
    int h = threadIdx.x >> 5, i = threadIdx.x & 31;
    if (h >= heads) return;
    float p = (float)pos[s];
    float inv = powf(1.0e6f, -(float)(2 * i) / 64.f);
    float a = p * inv;
    float c = cosf(a), sn = sinf(a);
    float* xp = x + (size_t)s * heads * HDIM + h * HDIM;
    float x1 = xp[i], x2 = xp[i + 32];
    xp[i]      = x1 * c - x2 * sn;
    xp[i + 32] = x2 * c + x1 * sn;
}

// ---------------- causal attention, warp-per-query-row online softmax ----------------
__global__ void attn_kernel() {
    int head = blockIdx.x;
    int warp = threadIdx.x >> 5, lane = threadIdx.x & 31;
    int row = blockIdx.y * 8 + warp;
    int kvh = head >> 2;  // H/KH = 4
    const float* qp = g_q + (size_t)row * QD + head * HDIM;
    float q0 = qp[lane], q1 = qp[lane + 32];
    const float scale = 0.125f;  // 1/sqrt(64)
    float m = -1e30f, l = 0.f, o0 = 0.f, o1 = 0.f;
    const float* kbase = g_k + kvh * HDIM;
    const float* vbase = g_v + kvh * HDIM;
    for (int j = 0; j <= row; j++) {
        const float* kp = kbase + (size_t)j * KD;
        float part = q0 * kp[lane] + q1 * kp[lane + 32];
        part += __shfl_xor_sync(0xffffffffu, part, 16);
        part += __shfl_xor_sync(0xffffffffu, part, 8);
        part += __shfl_xor_sync(0xffffffffu, part, 4);
        part += __shfl_xor_sync(0xffffffffu, part, 2);
        part += __shfl_xor_sync(0xffffffffu, part, 1);
        float s = part * scale;
        float nm = fmaxf(m, s);
        float corr = expf(m - nm);
        float pw = expf(s - nm);
        l = l * corr + pw;
        const float* vp = vbase + (size_t)j * KD;
        o0 = o0 * corr + pw * vp[lane];
        o1 = o1 * corr + pw * vp[lane + 32];
        m = nm;
    }
    float inv = 1.f / l;
    float* op = g_attn + (size_t)row * QD + head * HDIM;
    op[lane] = o0 * inv;
    op[lane + 32] = o1 * inv;
}

// ---------------- router: softmax over 8 experts, top-2, build expert lists ----------------
__global__ void router_kernel(const float* __restrict__ X, const float* __restrict__ Wr) {
    int t = blockIdx.x;
    int wid = threadIdx.x >> 5, lane = threadIdx.x & 31;
    __shared__ float logits[NE];
    const float* x = X + (size_t)t * DMODEL;
    float s = 0.f;
    for (int d = lane; d < DMODEL; d += 32) s += x[d] * Wr[d * NE + wid];
    for (int off = 16; off > 0; off >>= 1) s += __shfl_xor_sync(0xffffffffu, s, off);
    if (lane == 0) logits[wid] = s;
    __syncthreads();
    if (threadIdx.x == 0) {
        float m = -1e30f;
        for (int e = 0; e < NE; e++) m = fmaxf(m, logits[e]);
        float p[NE], sum = 0.f;
        for (int e = 0; e < NE; e++) { p[e] = expf(logits[e] - m); sum += p[e]; }
        for (int e = 0; e < NE; e++) p[e] /= sum;
        int i1 = 0;
        for (int e = 1; e < NE; e++) if (p[e] > p[i1]) i1 = e;
        int i2 = (i1 == 0) ? 1 : 0;
        for (int e = 0; e < NE; e++) if (e != i1 && p[e] > p[i2]) i2 = e;
        float v1 = p[i1], v2 = p[i2], tot = v1 + v2;
        v1 /= tot; v2 /= tot;
        for (int e = 0; e < NE; e++) g_comb[t * NE + e] = 0.f;
        g_comb[t * NE + i1] = v1;
        g_comb[t * NE + i2] = v2;
        int pos = atomicAdd(&g_cnt[i1], 1); g_idx[i1 * NTOK + pos] = t;
        pos = atomicAdd(&g_cnt[i2], 1);     g_idx[i2 * NTOK + pos] = t;
    }
}

__global__ void zero_cnt_kernel() {
    if (threadIdx.x < NE) g_cnt[threadIdx.x] = 0;
}

__global__ void copy_kernel(const float* __restrict__ src, float* __restrict__ dst) {
    size_t i = (size_t)blockIdx.x * 256 + threadIdx.x;
    dst[i] = src[i];
}

__global__ void silu_mul_kernel(const int* __restrict__ cntp) {
    long total = (long)(*cntp) * FF;
    long i = (long)blockIdx.x * 256 + threadIdx.x;
    if (i < total) {
        float g = g_act[i], u = g_act2[i];
        g_act[i] = (g / (1.f + expf(-g))) * u;
    }
}

// ---------------- host ----------------
static void* sym_addr(const void* symbol) {
    void* p = nullptr;
    cudaGetSymbolAddress(&p, symbol);
    return p;
}

extern "C" void kernel_launch(void* const* d_in, const int* in_sizes, int n_in,
                              void* d_out, int out_size) {
    const float* hid = (const float*)d_in[0];
    const int*   pos = (const int*)d_in[1];
    const float* ln1 = (const float*)d_in[2];
    const float* Wq  = (const float*)d_in[3];
    const float* Wk  = (const float*)d_in[4];
    const float* Wv  = (const float*)d_in[5];
    const float* Wo  = (const float*)d_in[6];
    const float* ln2 = (const float*)d_in[7];
    const float* Wr  = (const float*)d_in[8];
    const float* W1  = (const float*)d_in[9];
    const float* W3  = (const float*)d_in[10];
    const float* W2  = (const float*)d_in[11];
    float* out = (float*)d_out;

    float* p_hn   = (float*)sym_addr(g_hn);
    float* p_q    = (float*)sym_addr(g_q);
    float* p_k    = (float*)sym_addr(g_k);
    float* p_v    = (float*)sym_addr(g_v);
    float* p_attn = (float*)sym_addr(g_attn);
    float* p_h1   = (float*)sym_addr(g_h1);
    float* p_hn2  = (float*)sym_addr(g_hn2);
    float* p_comb = (float*)sym_addr(g_comb);
    int*   p_cnt  = (int*)sym_addr(g_cnt);
    int*   p_idx  = (int*)sym_addr(g_idx);
    float* p_act  = (float*)sym_addr(g_act);
    float* p_act2 = (float*)sym_addr(g_act2);

    // 1) rmsnorm1
    rmsnorm_kernel<<<NTOK, 256>>>(hid, ln1, p_hn);
    // 2) QKV projections
    gemm128<false><<<dim3(QD / 128, NTOK / 128), 256>>>(p_hn, Wq, nullptr, p_q, NTOK, QD, DMODEL);
    gemm128<false><<<dim3(KD / 128, NTOK / 128), 256>>>(p_hn, Wk, nullptr, p_k, NTOK, KD, DMODEL);
    gemm128<false><<<dim3(KD / 128, NTOK / 128), 256>>>(p_hn, Wv, nullptr, p_v, NTOK, KD, DMODEL);
    // 3) RoPE
    rope_kernel<<<NTOK, NH * 32>>>(p_q, pos, NH);
    rope_kernel<<<NTOK, NKV * 32>>>(p_k, pos, NKV);
    // 4) attention
    attn_kernel<<<dim3(NH, NTOK / 8), 256>>>();
    // 5) O projection + residual
    gemm128<true><<<dim3(DMODEL / 128, NTOK / 128), 256>>>(p_attn, Wo, hid, p_h1, NTOK, DMODEL, DMODEL);
    // 6) rmsnorm2
    rmsnorm_kernel<<<NTOK, 256>>>(p_h1, ln2, p_hn2);
    // 7) router
    zero_cnt_kernel<<<1, 32>>>();
    router_kernel<<<NTOK, 256>>>(p_hn2, Wr);
    // 8) out = residual
    copy_kernel<<<(NTOK * DMODEL) / 256, 256>>>(p_h1, out);
    // 9) sparse MoE, expert by expert (stream-serialized: no atomics needed on out)
    for (int e = 0; e < NE; e++) {
        const float* W1e = W1 + (size_t)e * DMODEL * FF;
        const float* W3e = W3 + (size_t)e * DMODEL * FF;
        const float* W2e = W2 + (size_t)e * FF * DMODEL;
        const int* idx_e = p_idx + e * NTOK;
        const int* cnt_e = p_cnt + e;
        gemm_gather<<<dim3(FF / 128, NTOK / 128), 256>>>(p_hn2, W1e, p_act, idx_e, cnt_e, DMODEL, FF);
        gemm_gather<<<dim3(FF / 128, NTOK / 128), 256>>>(p_hn2, W3e, p_act2, idx_e, cnt_e, DMODEL, FF);
        silu_mul_kernel<<<(NTOK * FF) / 256, 256>>>(cnt_e);
        gemm_down<<<dim3(DMODEL / 128, NTOK / 128), 256>>>(p_act, W2e, out, idx_e, cnt_e, p_comb, e);
    }
}

// round 4
// speedup vs baseline: 1.5014x; 1.5014x over previous
#include <cuda_runtime.h>
#include <math.h>

#define NTOK 2048
#define DMODEL 2048
#define NH 32
#define NKV 8
#define HDIM 64
#define QD 2048   // NH*HDIM
#define KD 512    // NKV*HDIM
#define NE 8
#define FF 7168
#define RMS_EPS 1e-5f

#define BM 128
#define BN 128
#define BK 16
#define LDSS 136   // padded float stride for SMEM tiles

// ---------------- scratch (device globals: no allocations allowed) ----------------
__device__ float g_hn  [NTOK * DMODEL];   // rmsnorm1 out
__device__ float g_q   [NTOK * QD];
__device__ float g_k   [NTOK * KD];
__device__ float g_v   [NTOK * KD];
__device__ float g_attn[NTOK * QD];       // attention out (pre-Wo)
__device__ float g_h1  [NTOK * DMODEL];   // residual after attention
__device__ float g_hn2 [NTOK * DMODEL];   // rmsnorm2 out
__device__ float g_comb[NTOK * NE];       // combine weights
__device__ int   g_cnt [NE];
__device__ int   g_idx [NE * NTOK];
__device__ float g_act [NTOK * FF];       // gate -> silu(gate)*up
__device__ float g_act2[NTOK * FF];       // up

// ---------------- helpers ----------------
__device__ __forceinline__ unsigned f2tf32(float v) {
    unsigned u;
    asm("cvt.rna.tf32.f32 %0, %1;" : "=r"(u) : "f"(v));
    return u;
}

// split x into hi (tf32) + lo (tf32 of remainder): 3xTF32 scheme
__device__ __forceinline__ void split_tf32(float v, float& hi, float& lo) {
    float h = __uint_as_float(f2tf32(v));
    hi = h;
    lo = __uint_as_float(f2tf32(v - h));
}

__device__ __forceinline__ void mma_tf32(float* c, const unsigned* a, const unsigned* b) {
    asm volatile(
        "mma.sync.aligned.m16n8k8.row.col.f32.tf32.tf32.f32 "
        "{%0,%1,%2,%3}, {%4,%5,%6,%7}, {%8,%9}, {%0,%1,%2,%3};"
        : "+f"(c[0]), "+f"(c[1]), "+f"(c[2]), "+f"(c[3])
        : "r"(a[0]), "r"(a[1]), "r"(a[2]), "r"(a[3]), "r"(b[0]), "r"(b[1]));
}

// ---------------- 3xTF32 tensor-core GEMM ----------------
// MODE 0: C = A@B              (dense)
// MODE 1: C = A@B + R          (dense + residual)
// MODE 2: C[r] = X[idx[r]]@B   (gather rows, masked store, r < cnt)
// MODE 3: Out[idx[r]] += w[idx[r]] * (Act[r]@B)   (down-proj scatter)
template <int MODE>
__global__ void gemm_tf32(const float* __restrict__ A, const float* __restrict__ B,
                          const float* __restrict__ R, float* __restrict__ C,
                          const int* __restrict__ idx, const int* __restrict__ cntp,
                          const float* __restrict__ comb, int e,
                          int N, int K) {
    int cnt = 0;
    if (MODE >= 2) {
        cnt = *cntp;
        if ((int)(blockIdx.y * BM) >= cnt) return;
    }
    __shared__ float As[2][BK][LDSS];   // [hi/lo][k][m]
    __shared__ float Bs[2][BK][LDSS];   // [hi/lo][k][n]

    const int tid  = threadIdx.x;
    const int lane = tid & 31;
    const int wid  = tid >> 5;
    const int wm = (wid >> 2) * 64;       // warp row offset in tile
    const int wn = (wid & 3) * 32;        // warp col offset in tile
    const int lr = lane >> 2;             // 0..7
    const int lk = lane & 3;              // 0..3

    float acc[4][4][4];
#pragma unroll
    for (int i = 0; i < 4; i++)
#pragma unroll
        for (int j = 0; j < 4; j++)
#pragma unroll
            for (int q = 0; q < 4; q++) acc[i][j][q] = 0.f;

    // A load mapping: each thread loads 8 consecutive k of one row
    const int arow_l = tid >> 1;              // 0..127
    const int ak     = (tid & 1) * 8;         // 0 or 8
    int arow_g = blockIdx.y * BM + arow_l;
    if (MODE == 2) arow_g = idx[arow_g < cnt ? arow_g : 0];
    if (MODE == 3) arow_g = arow_g < cnt ? arow_g : 0;
    const float* Ap = A + (size_t)arow_g * K + ak;

    // B load mapping: thread covers (k = t>>5 and t>>5 + 8, n = (t&31)*4)
    const int bk  = tid >> 5;                 // 0..7
    const int bn4 = lane * 4;
    const float* Bp = B + (size_t)bk * N + blockIdx.x * BN + bn4;
    const size_t bstride8 = (size_t)8 * N;

    for (int k0 = 0; k0 < K; k0 += BK) {
        float4 a0 = *(const float4*)(Ap + k0);
        float4 a1 = *(const float4*)(Ap + k0 + 4);
        float4 b0 = *(const float4*)(Bp + (size_t)k0 * N);
        float4 b1 = *(const float4*)(Bp + (size_t)k0 * N + bstride8);
        __syncthreads();   // protect previous iteration's reads
        {
            float av[8] = {a0.x, a0.y, a0.z, a0.w, a1.x, a1.y, a1.z, a1.w};
#pragma unroll
            for (int t = 0; t < 8; t++) {
                float hi, lo;
                split_tf32(av[t], hi, lo);
                As[0][ak + t][arow_l] = hi;
                As[1][ak + t][arow_l] = lo;
            }
            float bv0[4] = {b0.x, b0.y, b0.z, b0.w};
            float bv1[4] = {b1.x, b1.y, b1.z, b1.w};
            float h0[4], l0[4], h1[4], l1[4];
#pragma unroll
            for (int t = 0; t < 4; t++) {
                split_tf32(bv0[t], h0[t], l0[t]);
                split_tf32(bv1[t], h1[t], l1[t]);
            }
            *(float4*)&Bs[0][bk][bn4]     = make_float4(h0[0], h0[1], h0[2], h0[3]);
            *(float4*)&Bs[1][bk][bn4]     = make_float4(l0[0], l0[1], l0[2], l0[3]);
            *(float4*)&Bs[0][bk + 8][bn4] = make_float4(h1[0], h1[1], h1[2], h1[3]);
            *(float4*)&Bs[1][bk + 8][bn4] = make_float4(l1[0], l1[1], l1[2], l1[3]);
        }
        __syncthreads();

#pragma unroll
        for (int ks = 0; ks < BK; ks += 8) {
            unsigned afh[4][4], afl[4][4], bfh[4][2], bfl[4][2];
#pragma unroll
            for (int i = 0; i < 4; i++) {
                int r = wm + i * 16 + lr;
                afh[i][0] = __float_as_uint(As[0][ks + lk][r]);
                afh[i][1] = __float_as_uint(As[0][ks + lk][r + 8]);
                afh[i][2] = __float_as_uint(As[0][ks + lk + 4][r]);
                afh[i][3] = __float_as_uint(As[0][ks + lk + 4][r + 8]);
                afl[i][0] = __float_as_uint(As[1][ks + lk][r]);
                afl[i][1] = __float_as_uint(As[1][ks + lk][r + 8]);
                afl[i][2] = __float_as_uint(As[1][ks + lk + 4][r]);
                afl[i][3] = __float_as_uint(As[1][ks + lk + 4][r + 8]);
            }
#pragma unroll
            for (int j = 0; j < 4; j++) {
                int cix = wn + j * 8 + lr;
                bfh[j][0] = __float_as_uint(Bs[0][ks + lk][cix]);
                bfh[j][1] = __float_as_uint(Bs[0][ks + lk + 4][cix]);
                bfl[j][0] = __float_as_uint(Bs[1][ks + lk][cix]);
                bfl[j][1] = __float_as_uint(Bs[1][ks + lk + 4][cix]);
            }
#pragma unroll
            for (int i = 0; i < 4; i++)
#pragma unroll
                for (int j = 0; j < 4; j++) {
                    mma_tf32(acc[i][j], afl[i], bfh[j]);   // lo*hi
                    mma_tf32(acc[i][j], afh[i], bfl[j]);   // hi*lo
                    mma_tf32(acc[i][j], afh[i], bfh[j]);   // hi*hi
                }
        }
    }

    // epilogue
#pragma unroll
    for (int i = 0; i < 4; i++) {
        int rl0 = wm + i * 16 + lr;
#pragma unroll
        for (int j = 0; j < 4; j++) {
            int cc = blockIdx.x * BN + wn + j * 8 + lk * 2;
#pragma unroll
            for (int half = 0; half < 2; half++) {
                int rloc = rl0 + half * 8;
                int rg = blockIdx.y * BM + rloc;
                float v0 = acc[i][j][half * 2 + 0];
                float v1 = acc[i][j][half * 2 + 1];
                if (MODE == 0) {
                    size_t off = (size_t)rg * N + cc;
                    C[off] = v0; C[off + 1] = v1;
                } else if (MODE == 1) {
                    size_t off = (size_t)rg * N + cc;
                    C[off] = v0 + R[off]; C[off + 1] = v1 + R[off + 1];
                } else if (MODE == 2) {
                    if (rg < cnt) {
                        size_t off = (size_t)rg * N + cc;
                        C[off] = v0; C[off + 1] = v1;
                    }
                } else {  // MODE 3
                    if (rg < cnt) {
                        int t = idx[rg];
                        float w = comb[t * NE + e];
                        size_t off = (size_t)t * DMODEL + cc;
                        C[off]     += w * v0;
                        C[off + 1] += w * v1;
                    }
                }
            }
        }
    }
}

// ---------------- rmsnorm ----------------
__global__ void rmsnorm_kernel(const float* __restrict__ x, const float* __restrict__ w,
                               float* __restrict__ y) {
    int row = blockIdx.x;
    int tid = threadIdx.x;
    const float* xr = x + (size_t)row * DMODEL;
    float s = 0.f;
    for (int i = tid; i < DMODEL; i += 256) { float v = xr[i]; s += v * v; }
    for (int off = 16; off > 0; off >>= 1) s += __shfl_xor_sync(0xffffffffu, s, off);
    __shared__ float sh[8];
    if ((tid & 31) == 0) sh[tid >> 5] = s;
    __syncthreads();
    float tot = 0.f;
    for (int k = 0; k < 8; k++) tot += sh[k];
    float inv = rsqrtf(tot / (float)DMODEL + RMS_EPS);
    float* yr = y + (size_t)row * DMODEL;
    for (int i = tid; i < DMODEL; i += 256) yr[i] = xr[i] * inv * w[i];
}

// ---------------- RoPE (in place) ----------------
__global__ void rope_kernel(float* x, const int* __restrict__ pos, int heads) {
    int s = blockIdx.x;
    int h = threadIdx.x >> 5, i = threadIdx.x & 31;
    if (h >= heads) return;
    float p = (float)pos[s];
    float inv = powf(1.0e6f, -(float)(2 * i) / 64.f);
    float a = p * inv;
    float c = cosf(a), sn = sinf(a);
    float* xp = x + (size_t)s * heads * HDIM + h * HDIM;
    float x1 = xp[i], x2 = xp[i + 32];
    xp[i]      = x1 * c - x2 * sn;
    xp[i + 32] = x2 * c + x1 * sn;
}

// ---------------- causal attention, warp-per-query-row online softmax ----------------
__global__ void attn_kernel() {
    int head = blockIdx.x;
    int warp = threadIdx.x >> 5, lane = threadIdx.x & 31;
    int row = blockIdx.y * 8 + warp;
    int kvh = head >> 2;  // H/KH = 4
    const float* qp = g_q + (size_t)row * QD + head * HDIM;
    float q0 = qp[lane], q1 = qp[lane + 32];
    const float scale = 0.125f;
    float m = -1e30f, l = 0.f, o0 = 0.f, o1 = 0.f;
    const float* kbase = g_k + kvh * HDIM;
    const float* vbase = g_v + kvh * HDIM;
    for (int j = 0; j <= row; j++) {
        const float* kp = kbase + (size_t)j * KD;
        float part = q0 * kp[lane] + q1 * kp[lane + 32];
        part += __shfl_xor_sync(0xffffffffu, part, 16);
        part += __shfl_xor_sync(0xffffffffu, part, 8);
        part += __shfl_xor_sync(0xffffffffu, part, 4);
        part += __shfl_xor_sync(0xffffffffu, part, 2);
        part += __shfl_xor_sync(0xffffffffu, part, 1);
        float s = part * scale;
        float nm = fmaxf(m, s);
        float corr = expf(m - nm);
        float pw = expf(s - nm);
        l = l * corr + pw;
        const float* vp = vbase + (size_t)j * KD;
        o0 = o0 * corr + pw * vp[lane];
        o1 = o1 * corr + pw * vp[lane + 32];
        m = nm;
    }
    float inv = 1.f / l;
    float* op = g_attn + (size_t)row * QD + head * HDIM;
    op[lane] = o0 * inv;
    op[lane + 32] = o1 * inv;
}

// ---------------- router ----------------
__global__ void router_kernel(const float* __restrict__ X, const float* __restrict__ Wr) {
    int t = blockIdx.x;
    int wid = threadIdx.x >> 5, lane = threadIdx.x & 31;
    __shared__ float logits[NE];
    const float* x = X + (size_t)t * DMODEL;
    float s = 0.f;
    for (int d = lane; d < DMODEL; d += 32) s += x[d] * Wr[d * NE + wid];
    for (int off = 16; off > 0; off >>= 1) s += __shfl_xor_sync(0xffffffffu, s, off);
    if (lane == 0) logits[wid] = s;
    __syncthreads();
    if (threadIdx.x == 0) {
        float m = -1e30f;
        for (int e = 0; e < NE; e++) m = fmaxf(m, logits[e]);
        float p[NE], sum = 0.f;
        for (int e = 0; e < NE; e++) { p[e] = expf(logits[e] - m); sum += p[e]; }
        for (int e = 0; e < NE; e++) p[e] /= sum;
        int i1 = 0;
        for (int e = 1; e < NE; e++) if (p[e] > p[i1]) i1 = e;
        int i2 = (i1 == 0) ? 1 : 0;
        for (int e = 0; e < NE; e++) if (e != i1 && p[e] > p[i2]) i2 = e;
        float v1 = p[i1], v2 = p[i2], tot = v1 + v2;
        v1 /= tot; v2 /= tot;
        for (int e = 0; e < NE; e++) g_comb[t * NE + e] = 0.f;
        g_comb[t * NE + i1] = v1;
        g_comb[t * NE + i2] = v2;
        int pos = atomicAdd(&g_cnt[i1], 1); g_idx[i1 * NTOK + pos] = t;
        pos = atomicAdd(&g_cnt[i2], 1);     g_idx[i2 * NTOK + pos] = t;
    }
}

__global__ void zero_cnt_kernel() {
    if (threadIdx.x < NE) g_cnt[threadIdx.x] = 0;
}

__global__ void copy_kernel(const float* __restrict__ src, float* __restrict__ dst) {
    size_t i = (size_t)blockIdx.x * 256 + threadIdx.x;
    dst[i] = src[i];
}

__global__ void silu_mul_kernel(const int* __restrict__ cntp) {
    long total = (long)(*cntp) * FF;
    long i = (long)blockIdx.x * 256 + threadIdx.x;
    if (i < total) {
        float g = g_act[i], u = g_act2[i];
        g_act[i] = (g / (1.f + expf(-g))) * u;
    }
}

// ---------------- host ----------------
static void* sym_addr(const void* symbol) {
    void* p = nullptr;
    cudaGetSymbolAddress(&p, symbol);
    return p;
}

extern "C" void kernel_launch(void* const* d_in, const int* in_sizes, int n_in,
                              void* d_out, int out_size) {
    const float* hid = (const float*)d_in[0];
    const int*   pos = (const int*)d_in[1];
    const float* ln1 = (const float*)d_in[2];
    const float* Wq  = (const float*)d_in[3];
    const float* Wk  = (const float*)d_in[4];
    const float* Wv  = (const float*)d_in[5];
    const float* Wo  = (const float*)d_in[6];
    const float* ln2 = (const float*)d_in[7];
    const float* Wr  = (const float*)d_in[8];
    const float* W1  = (const float*)d_in[9];
    const float* W3  = (const float*)d_in[10];
    const float* W2  = (const float*)d_in[11];
    float* out = (float*)d_out;

    float* p_hn   = (float*)sym_addr(g_hn);
    float* p_q    = (float*)sym_addr(g_q);
    float* p_k    = (float*)sym_addr(g_k);
    float* p_v    = (float*)sym_addr(g_v);
    float* p_attn = (float*)sym_addr(g_attn);
    float* p_h1   = (float*)sym_addr(g_h1);
    float* p_hn2  = (float*)sym_addr(g_hn2);
    float* p_comb = (float*)sym_addr(g_comb);
    int*   p_cnt  = (int*)sym_addr(g_cnt);
    int*   p_idx  = (int*)sym_addr(g_idx);
    float* p_act  = (float*)sym_addr(g_act);
    float* p_act2 = (float*)sym_addr(g_act2);

    // 1) rmsnorm1
    rmsnorm_kernel<<<NTOK, 256>>>(hid, ln1, p_hn);
    // 2) QKV projections (3xTF32 tensor cores)
    gemm_tf32<0><<<dim3(QD / BN, NTOK / BM), 256>>>(p_hn, Wq, nullptr, p_q, nullptr, nullptr, nullptr, 0, QD, DMODEL);
    gemm_tf32<0><<<dim3(KD / BN, NTOK / BM), 256>>>(p_hn, Wk, nullptr, p_k, nullptr, nullptr, nullptr, 0, KD, DMODEL);
    gemm_tf32<0><<<dim3(KD / BN, NTOK / BM), 256>>>(p_hn, Wv, nullptr, p_v, nullptr, nullptr, nullptr, 0, KD, DMODEL);
    // 3) RoPE
    rope_kernel<<<NTOK, NH * 32>>>(p_q, pos, NH);
    rope_kernel<<<NTOK, NKV * 32>>>(p_k, pos, NKV);
    // 4) attention
    attn_kernel<<<dim3(NH, NTOK / 8), 256>>>();
    // 5) O projection + residual
    gemm_tf32<1><<<dim3(DMODEL / BN, NTOK / BM), 256>>>(p_attn, Wo, hid, p_h1, nullptr, nullptr, nullptr, 0, DMODEL, DMODEL);
    // 6) rmsnorm2
    rmsnorm_kernel<<<NTOK, 256>>>(p_h1, ln2, p_hn2);
    // 7) router
    zero_cnt_kernel<<<1, 32>>>();
    router_kernel<<<NTOK, 256>>>(p_hn2, Wr);
    // 8) out = residual
    copy_kernel<<<(NTOK * DMODEL) / 256, 256>>>(p_h1, out);
    // 9) sparse MoE, expert by expert (default-stream serialized: plain += is safe)
    for (int e = 0; e < NE; e++) {
        const float* W1e = W1 + (size_t)e * DMODEL * FF;
        const float* W3e = W3 + (size_t)e * DMODEL * FF;
        const float* W2e = W2 + (size_t)e * FF * DMODEL;
        const int* idx_e = p_idx + e * NTOK;
        const int* cnt_e = p_cnt + e;
        gemm_tf32<2><<<dim3(FF / BN, NTOK / BM), 256>>>(p_hn2, W1e, nullptr, p_act,  idx_e, cnt_e, nullptr, 0, FF, DMODEL);
        gemm_tf32<2><<<dim3(FF / BN, NTOK / BM), 256>>>(p_hn2, W3e, nullptr, p_act2, idx_e, cnt_e, nullptr, 0, FF, DMODEL);
        silu_mul_kernel<<<(NTOK * FF) / 256, 256>>>(cnt_e);
        gemm_tf32<3><<<dim3(DMODEL / BN, NTOK / BM), 256>>>(p_act, W2e, nullptr, out, idx_e, cnt_e, p_comb, e, DMODEL, FF);
    }
}

// round 5
// speedup vs baseline: 2.2412x; 1.4927x over previous
#include <cuda_runtime.h>
#include <math.h>

#define NTOK 2048
#define DMODEL 2048
#define NH 32
#define NKV 8
#define HDIM 64
#define QD 2048   // NH*HDIM
#define KD 512    // NKV*HDIM
#define NE 8
#define FF 7168
#define NROWS (2 * NTOK)   // total expert rows (top-2)
#define RMS_EPS 1e-5f

#define BM 128
#define BN 128
#define BK 16
#define LDSS 136   // padded float stride for SMEM tiles

// ---------------- scratch (device globals: no allocations allowed) ----------------
__device__ float g_hn   [NTOK * DMODEL];   // rmsnorm1 out
__device__ float g_q    [NTOK * QD];
__device__ float g_k    [NTOK * KD];
__device__ float g_v    [NTOK * KD];
__device__ float g_attn [NTOK * QD];       // attention out (pre-Wo)
__device__ float g_h1   [NTOK * DMODEL];   // residual after attention
__device__ float g_hn2  [NTOK * DMODEL];   // rmsnorm2 out
__device__ float g_comb [NTOK * NE];       // combine weights
__device__ int   g_cnt  [NE];
__device__ int   g_off  [NE];
__device__ int   g_idx  [NE * NTOK];
__device__ int   g_tokexp[NTOK * 2];       // per-token: its 2 experts
__device__ int   g_tokpos[NTOK * 2];       // per-token: its row pos within each expert list
__device__ float g_actc [NROWS * FF];      // compact gate -> silu(gate)*up
__device__ float g_act2c[NROWS * FF];      // compact up
__device__ float g_downc[NROWS * DMODEL];  // compact down-proj rows

// ---------------- helpers ----------------
__device__ __forceinline__ unsigned f2tf32(float v) {
    unsigned u;
    asm("cvt.rna.tf32.f32 %0, %1;" : "=r"(u) : "f"(v));
    return u;
}

__device__ __forceinline__ void split_tf32(float v, float& hi, float& lo) {
    float h = __uint_as_float(f2tf32(v));
    hi = h;
    lo = __uint_as_float(f2tf32(v - h));
}

__device__ __forceinline__ void mma_tf32(float* c, const unsigned* a, const unsigned* b) {
    asm volatile(
        "mma.sync.aligned.m16n8k8.row.col.f32.tf32.tf32.f32 "
        "{%0,%1,%2,%3}, {%4,%5,%6,%7}, {%8,%9}, {%0,%1,%2,%3};"
        : "+f"(c[0]), "+f"(c[1]), "+f"(c[2]), "+f"(c[3])
        : "r"(a[0]), "r"(a[1]), "r"(a[2]), "r"(a[3]), "r"(b[0]), "r"(b[1]));
}

// ---------------- 3xTF32 tensor-core GEMM ----------------
// MODE 1: O-proj + residual:  Cq = A@Bq + R        (grid: DMODEL/BN x NTOK/BM)
// MODE 2: MoE gate/up fused over experts:          (grid: 112 x 16 x NE)
//         z=e, x<56: g_actc[off+r] = hn2[idx]@W1e ; x>=56: g_act2c = ..@W3e
// MODE 3: MoE down fused over experts:             (grid: 16 x 16 x NE)
//         g_downc[off+r] = g_actc[off+r] @ W2e
// MODE 4: QKV fused:                               (grid: 24 x 16)
//         x<16: g_q = hn@Wq; x<20: g_k = hn@Wk; else g_v = hn@Wv
template <int MODE>
__global__ void __launch_bounds__(256, 2)
gemm3t(const float* __restrict__ A, const float* __restrict__ Bq,
       const float* __restrict__ Bk2, const float* __restrict__ Bv,
       const float* __restrict__ R, float* __restrict__ Cq,
       float* __restrict__ Ck, float* __restrict__ Cv,
       int Nq, int K) {
    // ---- mode-specific setup ----
    int cnt = 0, off = 0;
    const float* Bsel = Bq;
    float* Csel = Cq;
    int N = Nq;          // B row stride / C col count
    int ncol0 = blockIdx.x * BN;
    const int by = blockIdx.y;

    if (MODE == 2) {
        int e = blockIdx.z;
        cnt = g_cnt[e];
        if ((int)(by * BM) >= cnt) return;
        off = g_off[e];
        int xb = (blockIdx.x < 56) ? blockIdx.x : blockIdx.x - 56;
        ncol0 = xb * BN;
        N = FF;
        if (blockIdx.x < 56) { Bsel = Bq  + (size_t)e * DMODEL * FF; Csel = Cq; }
        else                 { Bsel = Bk2 + (size_t)e * DMODEL * FF; Csel = Ck; }
    } else if (MODE == 3) {
        int e = blockIdx.z;
        cnt = g_cnt[e];
        if ((int)(by * BM) >= cnt) return;
        off = g_off[e];
        Bsel = Bq + (size_t)e * FF * DMODEL;
        N = DMODEL;
    } else if (MODE == 4) {
        if (blockIdx.x < 16)      { Bsel = Bq;  Csel = Cq; N = QD; ncol0 = blockIdx.x * BN; }
        else if (blockIdx.x < 20) { Bsel = Bk2; Csel = Ck; N = KD; ncol0 = (blockIdx.x - 16) * BN; }
        else                      { Bsel = Bv;  Csel = Cv; N = KD; ncol0 = (blockIdx.x - 20) * BN; }
    }

    __shared__ float As[2][BK][LDSS];   // [hi/lo][k][m]
    __shared__ float Bs[2][BK][LDSS];   // [hi/lo][k][n]

    const int tid  = threadIdx.x;
    const int lane = tid & 31;
    const int wid  = tid >> 5;
    const int wm = (wid >> 2) * 64;
    const int wn = (wid & 3) * 32;
    const int lr = lane >> 2;
    const int lk = lane & 3;

    float acc[4][4][4];
#pragma unroll
    for (int i = 0; i < 4; i++)
#pragma unroll
        for (int j = 0; j < 4; j++)
#pragma unroll
            for (int q = 0; q < 4; q++) acc[i][j][q] = 0.f;

    // A load mapping: each thread loads 16 consecutive k of one row (two float4 pairs)
    const int arow_l = tid >> 1;
    const int ak     = (tid & 1) * 8;
    int r0 = by * BM + arow_l;
    const float* Ap;
    if (MODE == 2) {
        int rr = r0 < cnt ? r0 : cnt - 1;
        int token = g_idx[blockIdx.z * NTOK + rr];
        Ap = g_hn2 + (size_t)token * K + ak;
    } else if (MODE == 3) {
        int rr = r0 < cnt ? r0 : cnt - 1;
        Ap = g_actc + (size_t)(off + rr) * K + ak;
    } else {
        Ap = A + (size_t)r0 * K + ak;
    }

    const int bk  = tid >> 5;
    const int bn4 = lane * 4;
    const float* Bp = Bsel + (size_t)bk * N + ncol0 + bn4;
    const size_t bstride8 = (size_t)8 * N;

    for (int k0 = 0; k0 < K; k0 += BK) {
        float4 a0 = *(const float4*)(Ap + k0);
        float4 a1 = *(const float4*)(Ap + k0 + 4);
        float4 b0 = *(const float4*)(Bp + (size_t)k0 * N);
        float4 b1 = *(const float4*)(Bp + (size_t)k0 * N + bstride8);
        __syncthreads();
        {
            float av[8] = {a0.x, a0.y, a0.z, a0.w, a1.x, a1.y, a1.z, a1.w};
#pragma unroll
            for (int t = 0; t < 8; t++) {
                float hi, lo;
                split_tf32(av[t], hi, lo);
                As[0][ak + t][arow_l] = hi;
                As[1][ak + t][arow_l] = lo;
            }
            float bv0[4] = {b0.x, b0.y, b0.z, b0.w};
            float bv1[4] = {b1.x, b1.y, b1.z, b1.w};
            float h0[4], l0[4], h1[4], l1[4];
#pragma unroll
            for (int t = 0; t < 4; t++) {
                split_tf32(bv0[t], h0[t], l0[t]);
                split_tf32(bv1[t], h1[t], l1[t]);
            }
            *(float4*)&Bs[0][bk][bn4]     = make_float4(h0[0], h0[1], h0[2], h0[3]);
            *(float4*)&Bs[1][bk][bn4]     = make_float4(l0[0], l0[1], l0[2], l0[3]);
            *(float4*)&Bs[0][bk + 8][bn4] = make_float4(h1[0], h1[1], h1[2], h1[3]);
            *(float4*)&Bs[1][bk + 8][bn4] = make_float4(l1[0], l1[1], l1[2], l1[3]);
        }
        __syncthreads();

#pragma unroll
        for (int ks = 0; ks < BK; ks += 8) {
            unsigned afh[4][4], afl[4][4], bfh[4][2], bfl[4][2];
#pragma unroll
            for (int i = 0; i < 4; i++) {
                int r = wm + i * 16 + lr;
                afh[i][0] = __float_as_uint(As[0][ks + lk][r]);
                afh[i][1] = __float_as_uint(As[0][ks + lk][r + 8]);
                afh[i][2] = __float_as_uint(As[0][ks + lk + 4][r]);
                afh[i][3] = __float_as_uint(As[0][ks + lk + 4][r + 8]);
                afl[i][0] = __float_as_uint(As[1][ks + lk][r]);
                afl[i][1] = __float_as_uint(As[1][ks + lk][r + 8]);
                afl[i][2] = __float_as_uint(As[1][ks + lk + 4][r]);
                afl[i][3] = __float_as_uint(As[1][ks + lk + 4][r + 8]);
            }
#pragma unroll
            for (int j = 0; j < 4; j++) {
                int cix = wn + j * 8 + lr;
                bfh[j][0] = __float_as_uint(Bs[0][ks + lk][cix]);
                bfh[j][1] = __float_as_uint(Bs[0][ks + lk + 4][cix]);
                bfl[j][0] = __float_as_uint(Bs[1][ks + lk][cix]);
                bfl[j][1] = __float_as_uint(Bs[1][ks + lk + 4][cix]);
            }
#pragma unroll
            for (int i = 0; i < 4; i++)
#pragma unroll
                for (int j = 0; j < 4; j++) {
                    mma_tf32(acc[i][j], afl[i], bfh[j]);   // lo*hi
                    mma_tf32(acc[i][j], afh[i], bfl[j]);   // hi*lo
                    mma_tf32(acc[i][j], afh[i], bfh[j]);   // hi*hi
                }
        }
    }

    // ---- epilogue ----
#pragma unroll
    for (int i = 0; i < 4; i++) {
        int rl0 = wm + i * 16 + lr;
#pragma unroll
        for (int j = 0; j < 4; j++) {
            int cc = ncol0 + wn + j * 8 + lk * 2;
#pragma unroll
            for (int half = 0; half < 2; half++) {
                int rloc = rl0 + half * 8;
                int rg = by * BM + rloc;
                float v0 = acc[i][j][half * 2 + 0];
                float v1 = acc[i][j][half * 2 + 1];
                if (MODE == 1) {
                    size_t offc = (size_t)rg * N + cc;
                    Cq[offc] = v0 + R[offc];
                    Cq[offc + 1] = v1 + R[offc + 1];
                } else if (MODE == 2) {
                    if (rg < cnt) {
                        size_t offc = (size_t)(off + rg) * FF + cc;
                        Csel[offc] = v0; Csel[offc + 1] = v1;
                    }
                } else if (MODE == 3) {
                    if (rg < cnt) {
                        size_t offc = (size_t)(off + rg) * DMODEL + cc;
                        g_downc[offc] = v0; g_downc[offc + 1] = v1;
                    }
                } else {  // MODE 4
                    size_t offc = (size_t)rg * N + cc;
                    Csel[offc] = v0; Csel[offc + 1] = v1;
                }
            }
        }
    }
}

// ---------------- rmsnorm ----------------
__global__ void rmsnorm_kernel(const float* __restrict__ x, const float* __restrict__ w,
                               float* __restrict__ y) {
    int row = blockIdx.x;
    int tid = threadIdx.x;
    const float* xr = x + (size_t)row * DMODEL;
    float s = 0.f;
    for (int i = tid; i < DMODEL; i += 256) { float v = xr[i]; s += v * v; }
    for (int off = 16; off > 0; off >>= 1) s += __shfl_xor_sync(0xffffffffu, s, off);
    __shared__ float sh[8];
    if ((tid & 31) == 0) sh[tid >> 5] = s;
    __syncthreads();
    float tot = 0.f;
    for (int k = 0; k < 8; k++) tot += sh[k];
    float inv = rsqrtf(tot / (float)DMODEL + RMS_EPS);
    float* yr = y + (size_t)row * DMODEL;
    for (int i = tid; i < DMODEL; i += 256) yr[i] = xr[i] * inv * w[i];
}

// ---------------- RoPE (in place) ----------------
__global__ void rope_kernel(float* x, const int* __restrict__ pos, int heads) {
    int s = blockIdx.x;
    int h = threadIdx.x >> 5, i = threadIdx.x & 31;
    if (h >= heads) return;
    float p = (float)pos[s];
    float inv = powf(1.0e6f, -(float)(2 * i) / 64.f);
    float a = p * inv;
    float c = cosf(a), sn = sinf(a);
    float* xp = x + (size_t)s * heads * HDIM + h * HDIM;
    float x1 = xp[i], x2 = xp[i + 32];
    xp[i]      = x1 * c - x2 * sn;
    xp[i + 32] = x2 * c + x1 * sn;
}

// ---------------- causal attention, warp-per-query-row online softmax ----------------
__global__ void attn_kernel() {
    int head = blockIdx.x;
    int warp = threadIdx.x >> 5, lane = threadIdx.x & 31;
    int row = blockIdx.y * 8 + warp;
    int kvh = head >> 2;  // H/KH = 4
    const float* qp = g_q + (size_t)row * QD + head * HDIM;
    float q0 = qp[lane], q1 = qp[lane + 32];
    const float scale = 0.125f;
    float m = -1e30f, l = 0.f, o0 = 0.f, o1 = 0.f;
    const float* kbase = g_k + kvh * HDIM;
    const float* vbase = g_v + kvh * HDIM;
    for (int j = 0; j <= row; j++) {
        const float* kp = kbase + (size_t)j * KD;
        float part = q0 * kp[lane] + q1 * kp[lane + 32];
        part += __shfl_xor_sync(0xffffffffu, part, 16);
        part += __shfl_xor_sync(0xffffffffu, part, 8);
        part += __shfl_xor_sync(0xffffffffu, part, 4);
        part += __shfl_xor_sync(0xffffffffu, part, 2);
        part += __shfl_xor_sync(0xffffffffu, part, 1);
        float s = part * scale;
        float nm = fmaxf(m, s);
        float corr = expf(m - nm);
        float pw = expf(s - nm);
        l = l * corr + pw;
        const float* vp = vbase + (size_t)j * KD;
        o0 = o0 * corr + pw * vp[lane];
        o1 = o1 * corr + pw * vp[lane + 32];
        m = nm;
    }
    float inv = 1.f / l;
    float* op = g_attn + (size_t)row * QD + head * HDIM;
    op[lane] = o0 * inv;
    op[lane + 32] = o1 * inv;
}

// ---------------- router ----------------
__global__ void router_kernel(const float* __restrict__ X, const float* __restrict__ Wr) {
    int t = blockIdx.x;
    int wid = threadIdx.x >> 5, lane = threadIdx.x & 31;
    __shared__ float logits[NE];
    const float* x = X + (size_t)t * DMODEL;
    float s = 0.f;
    for (int d = lane; d < DMODEL; d += 32) s += x[d] * Wr[d * NE + wid];
    for (int off = 16; off > 0; off >>= 1) s += __shfl_xor_sync(0xffffffffu, s, off);
    if (lane == 0) logits[wid] = s;
    __syncthreads();
    if (threadIdx.x == 0) {
        float m = -1e30f;
        for (int e = 0; e < NE; e++) m = fmaxf(m, logits[e]);
        float p[NE], sum = 0.f;
        for (int e = 0; e < NE; e++) { p[e] = expf(logits[e] - m); sum += p[e]; }
        for (int e = 0; e < NE; e++) p[e] /= sum;
        int i1 = 0;
        for (int e = 1; e < NE; e++) if (p[e] > p[i1]) i1 = e;
        int i2 = (i1 == 0) ? 1 : 0;
        for (int e = 0; e < NE; e++) if (e != i1 && p[e] > p[i2]) i2 = e;
        float v1 = p[i1], v2 = p[i2], tot = v1 + v2;
        v1 /= tot; v2 /= tot;
        for (int e = 0; e < NE; e++) g_comb[t * NE + e] = 0.f;
        g_comb[t * NE + i1] = v1;
        g_comb[t * NE + i2] = v2;
        int pos1 = atomicAdd(&g_cnt[i1], 1); g_idx[i1 * NTOK + pos1] = t;
        int pos2 = atomicAdd(&g_cnt[i2], 1); g_idx[i2 * NTOK + pos2] = t;
        g_tokexp[t * 2 + 0] = i1; g_tokpos[t * 2 + 0] = pos1;
        g_tokexp[t * 2 + 1] = i2; g_tokpos[t * 2 + 1] = pos2;
    }
}

__global__ void zero_cnt_kernel() {
    if (threadIdx.x < NE) g_cnt[threadIdx.x] = 0;
}

__global__ void scan_kernel() {
    if (threadIdx.x == 0) {
        int s = 0;
        for (int e = 0; e < NE; e++) { g_off[e] = s; s += g_cnt[e]; }
    }
}

// silu(gate)*up over the full compact buffer (always NROWS rows)
__global__ void silu_mul_kernel() {
    size_t i = ((size_t)blockIdx.x * 256 + threadIdx.x) * 4;
    float4 g = *(float4*)&g_actc[i];
    float4 u = *(float4*)&g_act2c[i];
    g.x = (g.x / (1.f + expf(-g.x))) * u.x;
    g.y = (g.y / (1.f + expf(-g.y))) * u.y;
    g.z = (g.z / (1.f + expf(-g.z))) * u.z;
    g.w = (g.w / (1.f + expf(-g.w))) * u.w;
    *(float4*)&g_actc[i] = g;
}

// out[t] = h1[t] + w0*down_row(t,0) + w1*down_row(t,1)
__global__ void combine_kernel(float* __restrict__ out) {
    int t = blockIdx.x;
    int e0 = g_tokexp[t * 2 + 0], e1 = g_tokexp[t * 2 + 1];
    size_t r0 = (size_t)(g_off[e0] + g_tokpos[t * 2 + 0]) * DMODEL;
    size_t r1 = (size_t)(g_off[e1] + g_tokpos[t * 2 + 1]) * DMODEL;
    float w0 = g_comb[t * NE + e0], w1 = g_comb[t * NE + e1];
    size_t base = (size_t)t * DMODEL;
    for (int d = threadIdx.x * 4; d < DMODEL; d += 256 * 4) {
        float4 h = *(float4*)&g_h1[base + d];
        float4 d0 = *(float4*)&g_downc[r0 + d];
        float4 d1 = *(float4*)&g_downc[r1 + d];
        h.x += w0 * d0.x + w1 * d1.x;
        h.y += w0 * d0.y + w1 * d1.y;
        h.z += w0 * d0.z + w1 * d1.z;
        h.w += w0 * d0.w + w1 * d1.w;
        *(float4*)&out[base + d] = h;
    }
}

// ---------------- host ----------------
static void* sym_addr(const void* symbol) {
    void* p = nullptr;
    cudaGetSymbolAddress(&p, symbol);
    return p;
}

extern "C" void kernel_launch(void* const* d_in, const int* in_sizes, int n_in,
                              void* d_out, int out_size) {
    const float* hid = (const float*)d_in[0];
    const int*   pos = (const int*)d_in[1];
    const float* ln1 = (const float*)d_in[2];
    const float* Wq  = (const float*)d_in[3];
    const float* Wk  = (const float*)d_in[4];
    const float* Wv  = (const float*)d_in[5];
    const float* Wo  = (const float*)d_in[6];
    const float* ln2 = (const float*)d_in[7];
    const float* Wr  = (const float*)d_in[8];
    const float* W1  = (const float*)d_in[9];
    const float* W3  = (const float*)d_in[10];
    const float* W2  = (const float*)d_in[11];
    float* out = (float*)d_out;

    float* p_hn   = (float*)sym_addr(g_hn);
    float* p_q    = (float*)sym_addr(g_q);
    float* p_k    = (float*)sym_addr(g_k);
    float* p_v    = (float*)sym_addr(g_v);
    float* p_attn = (float*)sym_addr(g_attn);
    float* p_h1   = (float*)sym_addr(g_h1);
    float* p_hn2  = (float*)sym_addr(g_hn2);
    float* p_actc = (float*)sym_addr(g_actc);
    float* p_act2c= (float*)sym_addr(g_act2c);

    // 1) rmsnorm1
    rmsnorm_kernel<<<NTOK, 256>>>(hid, ln1, p_hn);
    // 2) fused QKV projection (3xTF32)
    gemm3t<4><<<dim3(24, NTOK / BM), 256>>>(p_hn, Wq, Wk, Wv, nullptr, p_q, p_k, p_v, QD, DMODEL);
    // 3) RoPE
    rope_kernel<<<NTOK, NH * 32>>>(p_q, pos, NH);
    rope_kernel<<<NTOK, NKV * 32>>>(p_k, pos, NKV);
    // 4) attention
    attn_kernel<<<dim3(NH, NTOK / 8), 256>>>();
    // 5) O projection + residual
    gemm3t<1><<<dim3(DMODEL / BN, NTOK / BM), 256>>>(p_attn, Wo, nullptr, nullptr, hid, p_h1, nullptr, nullptr, DMODEL, DMODEL);
    // 6) rmsnorm2
    rmsnorm_kernel<<<NTOK, 256>>>(p_h1, ln2, p_hn2);
    // 7) router + offsets
    zero_cnt_kernel<<<1, 32>>>();
    router_kernel<<<NTOK, 256>>>(p_hn2, Wr);
    scan_kernel<<<1, 32>>>();
    // 8) fused MoE gate+up over all experts (one launch)
    gemm3t<2><<<dim3(112, NTOK / BM, NE), 256>>>(nullptr, W1, W3, nullptr, nullptr, p_actc, p_act2c, nullptr, FF, DMODEL);
    // 9) silu(gate)*up over compact buffer (exactly NROWS rows, fixed size)
    silu_mul_kernel<<<(NROWS * FF) / (256 * 4), 256>>>();
    // 10) fused down-proj over all experts (one launch)
    gemm3t<3><<<dim3(DMODEL / BN, NTOK / BM, NE), 256>>>(nullptr, W2, nullptr, nullptr, nullptr, nullptr, nullptr, nullptr, DMODEL, FF);
    // 11) combine: out = h1 + w0*down0 + w1*down1
    combine_kernel<<<NTOK, 256>>>(out);
}

// round 7
// speedup vs baseline: 2.5842x; 1.1531x over previous
#include <cuda_runtime.h>
#include <cuda_fp16.h>
#include <math.h>

#define NTOK 2048
#define DMODEL 2048
#define NH 32
#define NKV 8
#define HDIM 64
#define QD 2048   // NH*HDIM
#define KD 512    // NKV*HDIM
#define NE 8
#define FF 7168
#define NROWS (2 * NTOK)   // total expert rows (top-2)
#define RMS_EPS 1e-5f

#define BM 128
#define BN 128
#define BK 16
#define LDSS 136   // padded word stride for SMEM tiles (div by 4 for uint4 stores)

// ---------------- scratch (device globals: no allocations allowed) ----------------
__device__ float g_hn   [NTOK * DMODEL];   // rmsnorm1 out
__device__ float g_q    [NTOK * QD];
__device__ float g_k    [NTOK * KD];
__device__ float g_v    [NTOK * KD];
__device__ float g_attn [NTOK * QD];       // attention out (pre-Wo)
__device__ float g_h1   [NTOK * DMODEL];   // residual after attention
__device__ float g_hn2  [NTOK * DMODEL];   // rmsnorm2 out
__device__ float g_comb [NTOK * NE];       // combine weights
__device__ int   g_cnt  [NE];
__device__ int   g_off  [NE];
__device__ int   g_idx  [NE * NTOK];
__device__ int   g_tokexp[NTOK * 2];
__device__ int   g_tokpos[NTOK * 2];
__device__ float g_actc [NROWS * FF];      // compact gate -> silu(gate)*up
__device__ float g_act2c[NROWS * FF];      // compact up
__device__ float g_downc[NROWS * DMODEL];  // compact down-proj rows

// ---------------- helpers ----------------
// fp16x3 split: x ~= hi + lo with hi,lo fp16; dropped lo*lo term ~2^-24
__device__ __forceinline__ void split_f16(float v, unsigned short& hi, unsigned short& lo) {
    __half h = __float2half_rn(v);
    __half l = __float2half_rn(v - __half2float(h));
    hi = __half_as_ushort(h);
    lo = __half_as_ushort(l);
}

__device__ __forceinline__ unsigned pack2(unsigned short a, unsigned short b) {
    return (unsigned)a | ((unsigned)b << 16);   // a in low half (k-even first)
}

__device__ __forceinline__ void mma_f16(float* c, const unsigned* a, const unsigned* b) {
    asm volatile(
        "mma.sync.aligned.m16n8k16.row.col.f32.f16.f16.f32 "
        "{%0,%1,%2,%3}, {%4,%5,%6,%7}, {%8,%9}, {%0,%1,%2,%3};"
        : "+f"(c[0]), "+f"(c[1]), "+f"(c[2]), "+f"(c[3])
        : "r"(a[0]), "r"(a[1]), "r"(a[2]), "r"(a[3]), "r"(b[0]), "r"(b[1]));
}

// ---------------- fp16x3 tensor-core GEMM, 128x128 tile, 4 warps (64x64 each) ----------------
// MODE 1: O-proj + residual:  Cq = A@Bq + R        (grid: DMODEL/BN x NTOK/BM)
// MODE 2: MoE gate/up fused over experts:          (grid: 112 x 16 x NE)
// MODE 3: MoE down fused over experts:             (grid: 16 x 16 x NE)
// MODE 4: QKV fused:                               (grid: 24 x 16)
template <int MODE>
__global__ void __launch_bounds__(128, 2)
gemm3h(const float* __restrict__ A, const float* __restrict__ Bq,
       const float* __restrict__ Bk2, const float* __restrict__ Bv,
       const float* __restrict__ R, float* __restrict__ Cq,
       float* __restrict__ Ck, float* __restrict__ Cv,
       int Nq, int K) {
    // ---- mode-specific setup ----
    int cnt = 0, off = 0;
    const float* Bsel = Bq;
    float* Csel = Cq;
    int N = Nq;
    int ncol0 = blockIdx.x * BN;
    const int by = blockIdx.y;

    if (MODE == 2) {
        int e = blockIdx.z;
        cnt = g_cnt[e];
        if ((int)(by * BM) >= cnt) return;
        off = g_off[e];
        int xb = (blockIdx.x < 56) ? blockIdx.x : blockIdx.x - 56;
        ncol0 = xb * BN;
        N = FF;
        if (blockIdx.x < 56) { Bsel = Bq  + (size_t)e * DMODEL * FF; Csel = Cq; }
        else                 { Bsel = Bk2 + (size_t)e * DMODEL * FF; Csel = Ck; }
    } else if (MODE == 3) {
        int e = blockIdx.z;
        cnt = g_cnt[e];
        if ((int)(by * BM) >= cnt) return;
        off = g_off[e];
        Bsel = Bq + (size_t)e * FF * DMODEL;
        N = DMODEL;
    } else if (MODE == 4) {
        if (blockIdx.x < 16)      { Bsel = Bq;  Csel = Cq; N = QD; ncol0 = blockIdx.x * BN; }
        else if (blockIdx.x < 20) { Bsel = Bk2; Csel = Ck; N = KD; ncol0 = (blockIdx.x - 16) * BN; }
        else                      { Bsel = Bv;  Csel = Cv; N = KD; ncol0 = (blockIdx.x - 20) * BN; }
    }

    // SMEM: half2-packed words; [plane hi/lo][k2 (k/2)][m or n]
    __shared__ __align__(16) unsigned As[2][BK / 2][LDSS];
    __shared__ __align__(16) unsigned Bs[2][BK / 2][LDSS];

    const int tid  = threadIdx.x;
    const int lane = tid & 31;
    const int wid  = tid >> 5;
    const int wm = (wid >> 1) * 64;       // warp row offset (2x2 warp grid)
    const int wn = (wid & 1) * 64;
    const int lr = lane >> 2;             // 0..7
    const int lk = lane & 3;              // 0..3

    float acc[4][8][4];
#pragma unroll
    for (int i = 0; i < 4; i++)
#pragma unroll
        for (int j = 0; j < 8; j++)
#pragma unroll
            for (int q = 0; q < 4; q++) acc[i][j][q] = 0.f;

    // ---- A loader: thread = one row, 16 consecutive k (4 float4) ----
    int r0 = by * BM + tid;
    const float* Ap;
    if (MODE == 2) {
        int rr = r0 < cnt ? r0 : cnt - 1;
        int token = g_idx[blockIdx.z * NTOK + rr];
        Ap = g_hn2 + (size_t)token * K;
    } else if (MODE == 3) {
        int rr = r0 < cnt ? r0 : cnt - 1;
        Ap = g_actc + (size_t)(off + rr) * K;
    } else {
        Ap = A + (size_t)r0 * K;
    }

    // ---- B loader: thread covers k-pair rows (2bk, 2bk+1), 8 cols ----
    const int bk = tid >> 4;              // 0..7
    const int c8 = (tid & 15) * 8;        // 0..120
    const float* Bp = Bsel + (size_t)(2 * bk) * N + ncol0 + c8;

    for (int k0 = 0; k0 < K; k0 += BK) {
        // global loads
        float4 a0 = *(const float4*)(Ap + k0);
        float4 a1 = *(const float4*)(Ap + k0 + 4);
        float4 a2 = *(const float4*)(Ap + k0 + 8);
        float4 a3 = *(const float4*)(Ap + k0 + 12);
        const float* bptr = Bp + (size_t)k0 * N;
        float4 be0 = *(const float4*)(bptr);
        float4 be1 = *(const float4*)(bptr + 4);
        float4 bo0 = *(const float4*)(bptr + N);
        float4 bo1 = *(const float4*)(bptr + N + 4);
        __syncthreads();   // protect previous iteration's fragment reads
        {
            float av[16] = {a0.x, a0.y, a0.z, a0.w, a1.x, a1.y, a1.z, a1.w,
                            a2.x, a2.y, a2.z, a2.w, a3.x, a3.y, a3.z, a3.w};
#pragma unroll
            for (int m = 0; m < 8; m++) {
                unsigned short h0, l0, h1, l1;
                split_f16(av[2 * m], h0, l0);
                split_f16(av[2 * m + 1], h1, l1);
                As[0][m][tid] = pack2(h0, h1);
                As[1][m][tid] = pack2(l0, l1);
            }
            float bev[8] = {be0.x, be0.y, be0.z, be0.w, be1.x, be1.y, be1.z, be1.w};
            float bov[8] = {bo0.x, bo0.y, bo0.z, bo0.w, bo1.x, bo1.y, bo1.z, bo1.w};
            unsigned wh[8], wl[8];
#pragma unroll
            for (int c = 0; c < 8; c++) {
                unsigned short he, le, ho, lo2;
                split_f16(bev[c], he, le);
                split_f16(bov[c], ho, lo2);
                wh[c] = pack2(he, ho);   // (k even, k odd)
                wl[c] = pack2(le, lo2);
            }
            *(uint4*)&Bs[0][bk][c8]     = make_uint4(wh[0], wh[1], wh[2], wh[3]);
            *(uint4*)&Bs[0][bk][c8 + 4] = make_uint4(wh[4], wh[5], wh[6], wh[7]);
            *(uint4*)&Bs[1][bk][c8]     = make_uint4(wl[0], wl[1], wl[2], wl[3]);
            *(uint4*)&Bs[1][bk][c8 + 4] = make_uint4(wl[4], wl[5], wl[6], wl[7]);
        }
        __syncthreads();

        // fragments + MMA (one k16 step)
        unsigned afh[4][4], afl[4][4], bfh[8][2], bfl[8][2];
#pragma unroll
        for (int i = 0; i < 4; i++) {
            int r = wm + i * 16 + lr;
            afh[i][0] = As[0][lk][r];
            afh[i][1] = As[0][lk][r + 8];
            afh[i][2] = As[0][lk + 4][r];
            afh[i][3] = As[0][lk + 4][r + 8];
            afl[i][0] = As[1][lk][r];
            afl[i][1] = As[1][lk][r + 8];
            afl[i][2] = As[1][lk + 4][r];
            afl[i][3] = As[1][lk + 4][r + 8];
        }
#pragma unroll
        for (int j = 0; j < 8; j++) {
            int c = wn + j * 8 + lr;
            bfh[j][0] = Bs[0][lk][c];
            bfh[j][1] = Bs[0][lk + 4][c];
            bfl[j][0] = Bs[1][lk][c];
            bfl[j][1] = Bs[1][lk + 4][c];
        }
#pragma unroll
        for (int i = 0; i < 4; i++)
#pragma unroll
            for (int j = 0; j < 8; j++) {
                mma_f16(acc[i][j], afl[i], bfh[j]);   // lo*hi
                mma_f16(acc[i][j], afh[i], bfl[j]);   // hi*lo
                mma_f16(acc[i][j], afh[i], bfh[j]);   // hi*hi
            }
    }

    // ---- epilogue ----
#pragma unroll
    for (int i = 0; i < 4; i++) {
        int rl0 = wm + i * 16 + lr;
#pragma unroll
        for (int j = 0; j < 8; j++) {
            int cc = ncol0 + wn + j * 8 + lk * 2;
#pragma unroll
            for (int half = 0; half < 2; half++) {
                int rloc = rl0 + half * 8;
                int rg = by * BM + rloc;
                float v0 = acc[i][j][half * 2 + 0];
                float v1 = acc[i][j][half * 2 + 1];
                if (MODE == 1) {
                    size_t offc = (size_t)rg * N + cc;
                    Cq[offc] = v0 + R[offc];
                    Cq[offc + 1] = v1 + R[offc + 1];
                } else if (MODE == 2) {
                    if (rg < cnt) {
                        size_t offc = (size_t)(off + rg) * FF + cc;
                        Csel[offc] = v0; Csel[offc + 1] = v1;
                    }
                } else if (MODE == 3) {
                    if (rg < cnt) {
                        size_t offc = (size_t)(off + rg) * DMODEL + cc;
                        g_downc[offc] = v0; g_downc[offc + 1] = v1;
                    }
                } else {  // MODE 4
                    size_t offc = (size_t)rg * N + cc;
                    Csel[offc] = v0; Csel[offc + 1] = v1;
                }
            }
        }
    }
}

// ---------------- rmsnorm ----------------
__global__ void rmsnorm_kernel(const float* __restrict__ x, const float* __restrict__ w,
                               float* __restrict__ y) {
    int row = blockIdx.x;
    int tid = threadIdx.x;
    const float* xr = x + (size_t)row * DMODEL;
    float s = 0.f;
    for (int i = tid; i < DMODEL; i += 256) { float v = xr[i]; s += v * v; }
    for (int off = 16; off > 0; off >>= 1) s += __shfl_xor_sync(0xffffffffu, s, off);
    __shared__ float sh[8];
    if ((tid & 31) == 0) sh[tid >> 5] = s;
    __syncthreads();
    float tot = 0.f;
    for (int k = 0; k < 8; k++) tot += sh[k];
    float inv = rsqrtf(tot / (float)DMODEL + RMS_EPS);
    float* yr = y + (size_t)row * DMODEL;
    for (int i = tid; i < DMODEL; i += 256) yr[i] = xr[i] * inv * w[i];
}

// ---------------- RoPE (in place) ----------------
__global__ void rope_kernel(float* x, const int* __restrict__ pos, int heads) {
    int s = blockIdx.x;
    int h = threadIdx.x >> 5, i = threadIdx.x & 31;
    if (h >= heads) return;
    float p = (float)pos[s];
    float inv = powf(1.0e6f, -(float)(2 * i) / 64.f);
    float a = p * inv;
    float c = cosf(a), sn = sinf(a);
    float* xp = x + (size_t)s * heads * HDIM + h * HDIM;
    float x1 = xp[i], x2 = xp[i + 32];
    xp[i]      = x1 * c - x2 * sn;
    xp[i + 32] = x2 * c + x1 * sn;
}

// ---------------- causal attention, warp-per-query-row online softmax ----------------
__global__ void attn_kernel() {
    int head = blockIdx.x;
    int warp = threadIdx.x >> 5, lane = threadIdx.x & 31;
    int row = blockIdx.y * 8 + warp;
    int kvh = head >> 2;  // H/KH = 4
    const float* qp = g_q + (size_t)row * QD + head * HDIM;
    float q0 = qp[lane], q1 = qp[lane + 32];
    const float scale = 0.125f;
    float m = -1e30f, l = 0.f, o0 = 0.f, o1 = 0.f;
    const float* kbase = g_k + kvh * HDIM;
    const float* vbase = g_v + kvh * HDIM;
    for (int j = 0; j <= row; j++) {
        const float* kp = kbase + (size_t)j * KD;
        float part = q0 * kp[lane] + q1 * kp[lane + 32];
        part += __shfl_xor_sync(0xffffffffu, part, 16);
        part += __shfl_xor_sync(0xffffffffu, part, 8);
        part += __shfl_xor_sync(0xffffffffu, part, 4);
        part += __shfl_xor_sync(0xffffffffu, part, 2);
        part += __shfl_xor_sync(0xffffffffu, part, 1);
        float s = part * scale;
        float nm = fmaxf(m, s);
        float corr = expf(m - nm);
        float pw = expf(s - nm);
        l = l * corr + pw;
        const float* vp = vbase + (size_t)j * KD;
        o0 = o0 * corr + pw * vp[lane];
        o1 = o1 * corr + pw * vp[lane + 32];
        m = nm;
    }
    float inv = 1.f / l;
    float* op = g_attn + (size_t)row * QD + head * HDIM;
    op[lane] = o0 * inv;
    op[lane + 32] = o1 * inv;
}

// ---------------- router ----------------
__global__ void router_kernel(const float* __restrict__ X, const float* __restrict__ Wr) {
    int t = blockIdx.x;
    int wid = threadIdx.x >> 5, lane = threadIdx.x & 31;
    __shared__ float logits[NE];
    const float* x = X + (size_t)t * DMODEL;
    float s = 0.f;
    for (int d = lane; d < DMODEL; d += 32) s += x[d] * Wr[d * NE + wid];
    for (int off = 16; off > 0; off >>= 1) s += __shfl_xor_sync(0xffffffffu, s, off);
    if (lane == 0) logits[wid] = s;
    __syncthreads();
    if (threadIdx.x == 0) {
        float m = -1e30f;
        for (int e = 0; e < NE; e++) m = fmaxf(m, logits[e]);
        float p[NE], sum = 0.f;
        for (int e = 0; e < NE; e++) { p[e] = expf(logits[e] - m); sum += p[e]; }
        for (int e = 0; e < NE; e++) p[e] /= sum;
        int i1 = 0;
        for (int e = 1; e < NE; e++) if (p[e] > p[i1]) i1 = e;
        int i2 = (i1 == 0) ? 1 : 0;
        for (int e = 0; e < NE; e++) if (e != i1 && p[e] > p[i2]) i2 = e;
        float v1 = p[i1], v2 = p[i2], tot = v1 + v2;
        v1 /= tot; v2 /= tot;
        for (int e = 0; e < NE; e++) g_comb[t * NE + e] = 0.f;
        g_comb[t * NE + i1] = v1;
        g_comb[t * NE + i2] = v2;
        int pos1 = atomicAdd(&g_cnt[i1], 1); g_idx[i1 * NTOK + pos1] = t;
        int pos2 = atomicAdd(&g_cnt[i2], 1); g_idx[i2 * NTOK + pos2] = t;
        g_tokexp[t * 2 + 0] = i1; g_tokpos[t * 2 + 0] = pos1;
        g_tokexp[t * 2 + 1] = i2; g_tokpos[t * 2 + 1] = pos2;
    }
}

__global__ void zero_cnt_kernel() {
    if (threadIdx.x < NE) g_cnt[threadIdx.x] = 0;
}

__global__ void scan_kernel() {
    if (threadIdx.x == 0) {
        int s = 0;
        for (int e = 0; e < NE; e++) { g_off[e] = s; s += g_cnt[e]; }
    }
}

// silu(gate)*up over the full compact buffer (always NROWS rows)
__global__ void silu_mul_kernel() {
    size_t i = ((size_t)blockIdx.x * 256 + threadIdx.x) * 4;
    float4 g = *(float4*)&g_actc[i];
    float4 u = *(float4*)&g_act2c[i];
    g.x = (g.x / (1.f + expf(-g.x))) * u.x;
    g.y = (g.y / (1.f + expf(-g.y))) * u.y;
    g.z = (g.z / (1.f + expf(-g.z))) * u.z;
    g.w = (g.w / (1.f + expf(-g.w))) * u.w;
    *(float4*)&g_actc[i] = g;
}

// out[t] = h1[t] + w0*down_row(t,0) + w1*down_row(t,1)
__global__ void combine_kernel(float* __restrict__ out) {
    int t = blockIdx.x;
    int e0 = g_tokexp[t * 2 + 0], e1 = g_tokexp[t * 2 + 1];
    size_t r0 = (size_t)(g_off[e0] + g_tokpos[t * 2 + 0]) * DMODEL;
    size_t r1 = (size_t)(g_off[e1] + g_tokpos[t * 2 + 1]) * DMODEL;
    float w0 = g_comb[t * NE + e0], w1 = g_comb[t * NE + e1];
    size_t base = (size_t)t * DMODEL;
    for (int d = threadIdx.x * 4; d < DMODEL; d += 256 * 4) {
        float4 h = *(float4*)&g_h1[base + d];
        float4 d0 = *(float4*)&g_downc[r0 + d];
        float4 d1 = *(float4*)&g_downc[r1 + d];
        h.x += w0 * d0.x + w1 * d1.x;
        h.y += w0 * d0.y + w1 * d1.y;
        h.z += w0 * d0.z + w1 * d1.z;
        h.w += w0 * d0.w + w1 * d1.w;
        *(float4*)&out[base + d] = h;
    }
}

// ---------------- host ----------------
static void* sym_addr(const void* symbol) {
    void* p = nullptr;
    cudaGetSymbolAddress(&p, symbol);
    return p;
}

extern "C" void kernel_launch(void* const* d_in, const int* in_sizes, int n_in,
                              void* d_out, int out_size) {
    const float* hid = (const float*)d_in[0];
    const int*   pos = (const int*)d_in[1];
    const float* ln1 = (const float*)d_in[2];
    const float* Wq  = (const float*)d_in[3];
    const float* Wk  = (const float*)d_in[4];
    const float* Wv  = (const float*)d_in[5];
    const float* Wo  = (const float*)d_in[6];
    const float* ln2 = (const float*)d_in[7];
    const float* Wr  = (const float*)d_in[8];
    const float* W1  = (const float*)d_in[9];
    const float* W3  = (const float*)d_in[10];
    const float* W2  = (const float*)d_in[11];
    float* out = (float*)d_out;

    float* p_hn   = (float*)sym_addr(g_hn);
    float* p_q    = (float*)sym_addr(g_q);
    float* p_k    = (float*)sym_addr(g_k);
    float* p_v    = (float*)sym_addr(g_v);
    float* p_attn = (float*)sym_addr(g_attn);
    float* p_h1   = (float*)sym_addr(g_h1);
    float* p_hn2  = (float*)sym_addr(g_hn2);
    float* p_actc = (float*)sym_addr(g_actc);
    float* p_act2c= (float*)sym_addr(g_act2c);

    // 1) rmsnorm1
    rmsnorm_kernel<<<NTOK, 256>>>(hid, ln1, p_hn);
    // 2) fused QKV projection (fp16x3)
    gemm3h<4><<<dim3(24, NTOK / BM), 128>>>(p_hn, Wq, Wk, Wv, nullptr, p_q, p_k, p_v, QD, DMODEL);
    // 3) RoPE
    rope_kernel<<<NTOK, NH * 32>>>(p_q, pos, NH);
    rope_kernel<<<NTOK, NKV * 32>>>(p_k, pos, NKV);
    // 4) attention
    attn_kernel<<<dim3(NH, NTOK / 8), 256>>>();
    // 5) O projection + residual
    gemm3h<1><<<dim3(DMODEL / BN, NTOK / BM), 128>>>(p_attn, Wo, nullptr, nullptr, hid, p_h1, nullptr, nullptr, DMODEL, DMODEL);
    // 6) rmsnorm2
    rmsnorm_kernel<<<NTOK, 256>>>(p_h1, ln2, p_hn2);
    // 7) router + offsets
    zero_cnt_kernel<<<1, 32>>>();
    router_kernel<<<NTOK, 256>>>(p_hn2, Wr);
    scan_kernel<<<1, 32>>>();
    // 8) fused MoE gate+up over all experts (one launch)
    gemm3h<2><<<dim3(112, NTOK / BM, NE), 128>>>(nullptr, W1, W3, nullptr, nullptr, p_actc, p_act2c, nullptr, FF, DMODEL);
    // 9) silu(gate)*up over compact buffer
    silu_mul_kernel<<<(NROWS * FF) / (256 * 4), 256>>>();
    // 10) fused down-proj over all experts (one launch)
    gemm3h<3><<<dim3(DMODEL / BN, NTOK / BM, NE), 128>>>(nullptr, W2, nullptr, nullptr, nullptr, nullptr, nullptr, nullptr, DMODEL, FF);
    // 11) combine: out = h1 + w0*down0 + w1*down1
    combine_kernel<<<NTOK, 256>>>(out);
}